// round 3
// baseline (speedup 1.0000x reference)
#include <cuda_runtime.h>
#include <cuda_bf16.h>
#include <math.h>

// ---------------- problem constants ----------------
#define QLEN   512
#define MLEN   512
#define KLEN   1024
#define BSZ    8
#define NH     16
#define DH     64
#define DM     1024
#define DI     4096
#define VOCAB  32000
#define NLAYER 6
#define MQ     (QLEN*BSZ)   // 4096 rows (i*8+b)
#define MK     (KLEN*BSZ)   // 8192 rows (j*8+b)
#define SCALE  0.125f       // 1/sqrt(64)
#define NEGV   (-1e30f)

// ---------------- scratch (device globals: no allocation allowed) ----------------
__device__ float g_core [MQ*DM];        // 16 MB
__device__ float g_xmem [MK*DM];        // 32 MB
__device__ float g_q    [MQ*DM];        // 16 MB
__device__ float g_kv   [MK*2*DM];      // 64 MB
__device__ float g_rk   [KLEN*DM];      // 4 MB
__device__ float g_pos  [KLEN*DM];      // 4 MB
__device__ float g_ac   [(size_t)BSZ*NH*QLEN*KLEN]; // 256 MB  (scores -> probs in place)
__device__ float g_bd   [(size_t)BSZ*NH*QLEN*KLEN]; // 256 MB
__device__ float g_vec  [MQ*DM];        // 16 MB
__device__ float g_tmp  [MQ*DM];        // 16 MB
__device__ float g_ff   [MQ*DI];        // 64 MB
__device__ float g_logits[(size_t)MQ*VOCAB];        // 512 MB

// ---------------- small helpers ----------------
__device__ __forceinline__ float blockReduceMax(float v, float* sm) {
    int tid = threadIdx.x;
    sm[tid] = v; __syncthreads();
    for (int s = 128; s > 0; s >>= 1) {
        if (tid < s) sm[tid] = fmaxf(sm[tid], sm[tid + s]);
        __syncthreads();
    }
    float r = sm[0]; __syncthreads();
    return r;
}
__device__ __forceinline__ float blockReduceSum(float v, float* sm) {
    int tid = threadIdx.x;
    sm[tid] = v; __syncthreads();
    for (int s = 128; s > 0; s >>= 1) {
        if (tid < s) sm[tid] += sm[tid + s];
        __syncthreads();
    }
    float r = sm[0]; __syncthreads();
    return r;
}

// ---------------- elementwise / setup kernels ----------------
__global__ void copy4_kernel(const float4* __restrict__ src, float4* __restrict__ dst, int n4) {
    int i = blockIdx.x * 256 + threadIdx.x;
    if (i < n4) dst[i] = src[i];
}

__global__ void embed_kernel(const int* __restrict__ data, const float* __restrict__ embW,
                             float* __restrict__ core, float* __restrict__ memout) {
    int r = blockIdx.x;                 // r = i*8+b
    int tok = data[r];
    float4 v = *(const float4*)(embW + (size_t)tok * DM + threadIdx.x * 4);
    *(float4*)(core   + (size_t)r * DM + threadIdx.x * 4) = v;
    *(float4*)(memout + (size_t)r * DM + threadIdx.x * 4) = v;
}

__global__ void pos_kernel(float* __restrict__ pos) {
    int x = blockIdx.x;                 // 0..1023 (key slot)
    double ps = (double)(KLEN - 1 - x); // pos_seq
    #pragma unroll
    for (int h = 0; h < 4; h++) {
        int c = threadIdx.x + 256 * h;
        int cp = (c < DM / 2) ? c : c - DM / 2;
        double invf = exp(-((double)(2 * cp) / (double)DM) * 9.210340371976184); // ln(10000)
        double a = ps * invf;
        pos[(size_t)x * DM + c] = (float)((c < DM / 2) ? sin(a) : cos(a));
    }
}

// core = LN(x + dx) * g + b ; optionally duplicate into memout
__global__ void add_ln_kernel(const float* __restrict__ x, const float* __restrict__ dx,
                              const float* __restrict__ g, const float* __restrict__ b,
                              float* __restrict__ out, float* __restrict__ memout) {
    __shared__ float sm[256];
    int r = blockIdx.x, tid = threadIdx.x;
    const float* xr = x  + (size_t)r * DM;
    const float* dr = dx + (size_t)r * DM;
    float v[4]; float sum = 0.f, sq = 0.f;
    #pragma unroll
    for (int h = 0; h < 4; h++) {
        int c = tid + 256 * h;
        v[h] = xr[c] + dr[c];
        sum += v[h]; sq += v[h] * v[h];
    }
    sum = blockReduceSum(sum, sm);
    sq  = blockReduceSum(sq, sm);
    float mean = sum * (1.f / DM);
    float var  = sq  * (1.f / DM) - mean * mean;
    float inv  = rsqrtf(var + 1e-5f);
    #pragma unroll
    for (int h = 0; h < 4; h++) {
        int c = tid + 256 * h;
        float y = (v[h] - mean) * inv * g[c] + b[c];
        out[(size_t)r * DM + c] = y;
        if (memout) memout[(size_t)r * DM + c] = y;
    }
}

// fused rel-shift + mask + scale + softmax. Reads AC and raw BD, writes probs over AC.
__global__ void score_softmax_kernel(const float* __restrict__ ac, const float* __restrict__ bd,
                                     float* __restrict__ prob) {
    __shared__ float sm[256];
    int i = blockIdx.x, bh = blockIdx.y, tid = threadIdx.x;
    const float* acr = ac + ((size_t)bh * QLEN + i) * KLEN;
    const float* bdr = bd + ((size_t)bh * QLEN + i) * KLEN;
    float* pr = prob + ((size_t)bh * QLEN + i) * KLEN;
    int lim = i + MLEN;                 // keys j <= lim are valid
    float s[4]; float mx = -1e30f;
    #pragma unroll
    for (int h = 0; h < 4; h++) {
        int j = tid + 256 * h;
        if (j <= lim) {
            s[h] = (acr[j] + bdr[j - i + (QLEN - 1)]) * SCALE; // verified rel_shift closed form
            mx = fmaxf(mx, s[h]);
        } else s[h] = NEGV;
    }
    mx = blockReduceMax(mx, sm);
    float sum = 0.f;
    #pragma unroll
    for (int h = 0; h < 4; h++) {
        int j = tid + 256 * h;
        if (j <= lim) { float e = expf(s[h] - mx); s[h] = e; sum += e; }
        else s[h] = 0.f;
    }
    sum = blockReduceSum(sum, sm);
    float inv = 1.f / sum;
    #pragma unroll
    for (int h = 0; h < 4; h++) {
        int j = tid + 256 * h;
        pr[j] = s[h] * inv;
    }
}

// per-row logsumexp - target logit
__global__ void loss_kernel(const float* __restrict__ logits, const int* __restrict__ target,
                            float* __restrict__ out) {
    __shared__ float sm[256];
    int r = blockIdx.x, tid = threadIdx.x;
    const float* row = logits + (size_t)r * VOCAB;
    float mx = -1e30f;
    for (int j = tid; j < VOCAB; j += 256) mx = fmaxf(mx, row[j]);
    mx = blockReduceMax(mx, sm);
    float sum = 0.f;
    for (int j = tid; j < VOCAB; j += 256) sum += expf(row[j] - mx);
    sum = blockReduceSum(sum, sm);
    if (tid == 0) out[r] = mx + logf(sum) - row[target[r]];
}

// ---------------- SGEMM (fp32, 128x128x16, 8x8/thread) ----------------
// C[M,N] = A[M,K] @ B[K,N]; flags: 1=add bias(len N), 2=also relu
__global__ __launch_bounds__(256) void gemm_nn(const float* __restrict__ A,
                                               const float* __restrict__ B,
                                               float* __restrict__ C,
                                               int M, int N, int K,
                                               const float* __restrict__ bias, int flags) {
    __shared__ float As[16][132];
    __shared__ float Bs[16][132];
    int bx = blockIdx.x, by = blockIdx.y, tid = threadIdx.x;
    const float* Ab = A + (size_t)by * 128 * K;
    const float* Bb = B + (size_t)bx * 128;
    int a_r = tid >> 2, a_c = (tid & 3) * 4;   // A: row 0..63(+64), k-off
    int b_r = tid >> 5, b_c = (tid & 31) * 4;  // B: k-row 0..7(+8), n-off
    int tr = tid >> 4, tc = tid & 15;
    float acc[8][8] = {};
    for (int k0 = 0; k0 < K; k0 += 16) {
        #pragma unroll
        for (int h = 0; h < 2; h++) {
            int r = a_r + h * 64;
            float4 v = *(const float4*)(Ab + (size_t)r * K + k0 + a_c);
            As[a_c + 0][r] = v.x; As[a_c + 1][r] = v.y;
            As[a_c + 2][r] = v.z; As[a_c + 3][r] = v.w;
        }
        #pragma unroll
        for (int h = 0; h < 2; h++) {
            int kr = b_r + h * 8;
            float4 v = *(const float4*)(Bb + (size_t)(k0 + kr) * N + b_c);
            *(float4*)&Bs[kr][b_c] = v;
        }
        __syncthreads();
        #pragma unroll
        for (int kk = 0; kk < 16; kk++) {
            float a[8], bb[8];
            #pragma unroll
            for (int i = 0; i < 8; i++) a[i] = As[kk][tr * 8 + i];
            #pragma unroll
            for (int j = 0; j < 8; j++) bb[j] = Bs[kk][tc * 8 + j];
            #pragma unroll
            for (int i = 0; i < 8; i++)
                #pragma unroll
                for (int j = 0; j < 8; j++)
                    acc[i][j] += a[i] * bb[j];
        }
        __syncthreads();
    }
    float* Cb = C + (size_t)by * 128 * N + (size_t)bx * 128;
    #pragma unroll
    for (int i = 0; i < 8; i++) {
        int r = tr * 8 + i;
        #pragma unroll
        for (int j = 0; j < 8; j++) {
            int c = tc * 8 + j;
            float v = acc[i][j];
            if (flags & 1) v += bias[(size_t)bx * 128 + c];
            if (flags & 2) v = fmaxf(v, 0.f);
            Cb[(size_t)r * N + c] = v;
        }
    }
}

// C[M,N] = A[M,K] @ B[N,K]^T  (for logits vs tied embedding)
__global__ __launch_bounds__(256) void gemm_nt(const float* __restrict__ A,
                                               const float* __restrict__ B,
                                               float* __restrict__ C,
                                               int M, int N, int K) {
    __shared__ float As[16][132];
    __shared__ float Bs[16][132];
    int bx = blockIdx.x, by = blockIdx.y, tid = threadIdx.x;
    const float* Ab = A + (size_t)by * 128 * K;
    const float* Bb = B + (size_t)bx * 128 * K;
    int a_r = tid >> 2, a_c = (tid & 3) * 4;
    int tr = tid >> 4, tc = tid & 15;
    float acc[8][8] = {};
    for (int k0 = 0; k0 < K; k0 += 16) {
        #pragma unroll
        for (int h = 0; h < 2; h++) {
            int r = a_r + h * 64;
            float4 va = *(const float4*)(Ab + (size_t)r * K + k0 + a_c);
            As[a_c + 0][r] = va.x; As[a_c + 1][r] = va.y;
            As[a_c + 2][r] = va.z; As[a_c + 3][r] = va.w;
            float4 vb = *(const float4*)(Bb + (size_t)r * K + k0 + a_c);
            Bs[a_c + 0][r] = vb.x; Bs[a_c + 1][r] = vb.y;
            Bs[a_c + 2][r] = vb.z; Bs[a_c + 3][r] = vb.w;
        }
        __syncthreads();
        #pragma unroll
        for (int kk = 0; kk < 16; kk++) {
            float a[8], bb[8];
            #pragma unroll
            for (int i = 0; i < 8; i++) a[i] = As[kk][tr * 8 + i];
            #pragma unroll
            for (int j = 0; j < 8; j++) bb[j] = Bs[kk][tc * 8 + j];
            #pragma unroll
            for (int i = 0; i < 8; i++)
                #pragma unroll
                for (int j = 0; j < 8; j++)
                    acc[i][j] += a[i] * bb[j];
        }
        __syncthreads();
    }
    float* Cb = C + (size_t)by * 128 * N + (size_t)bx * 128;
    #pragma unroll
    for (int i = 0; i < 8; i++)
        #pragma unroll
        for (int j = 0; j < 8; j++)
            Cb[(size_t)(tr * 8 + i) * N + tc * 8 + j] = acc[i][j];
}

// ---------------- batched attention GEMMs ----------------
// C[bh][i][j] = sum_d (A[i,d]+bias[d]) * B[j,d]   (K=64, per (b,n))
__global__ __launch_bounds__(256) void bgemm_qk(const float* __restrict__ A, long a_bstr, long a_nstr, long lda,
                                                const float* __restrict__ B, long b_bstr, long b_nstr, long ldb,
                                                const float* __restrict__ bias,
                                                float* __restrict__ C) {
    __shared__ float As[64][72];
    __shared__ float Bs[64][72];
    int bh = blockIdx.z, b = bh >> 4, n = bh & 15;
    int i0 = blockIdx.y * 64, j0 = blockIdx.x * 64;
    const float* Ap = A + (size_t)b * a_bstr + (size_t)n * a_nstr;
    const float* Bp = B + (size_t)b * b_bstr + (size_t)n * b_nstr;
    const float* bi = bias + n * 64;
    int tid = threadIdx.x;
    int lr = tid >> 4, lc = (tid & 15) * 4;
    #pragma unroll
    for (int h = 0; h < 4; h++) {
        int row = lr + 16 * h;
        float4 va = *(const float4*)(Ap + (size_t)(i0 + row) * lda + lc);
        va.x += bi[lc]; va.y += bi[lc + 1]; va.z += bi[lc + 2]; va.w += bi[lc + 3];
        As[lc + 0][row] = va.x; As[lc + 1][row] = va.y;
        As[lc + 2][row] = va.z; As[lc + 3][row] = va.w;
        float4 vb = *(const float4*)(Bp + (size_t)(j0 + row) * ldb + lc);
        Bs[lc + 0][row] = vb.x; Bs[lc + 1][row] = vb.y;
        Bs[lc + 2][row] = vb.z; Bs[lc + 3][row] = vb.w;
    }
    __syncthreads();
    int tr = (tid >> 4) * 4, tc = (tid & 15) * 4;
    float acc[4][4] = {};
    #pragma unroll
    for (int d = 0; d < 64; d++) {
        float4 a  = *(const float4*)&As[d][tr];
        float4 bb = *(const float4*)&Bs[d][tc];
        float av[4] = {a.x, a.y, a.z, a.w};
        float bv[4] = {bb.x, bb.y, bb.z, bb.w};
        #pragma unroll
        for (int i = 0; i < 4; i++)
            #pragma unroll
            for (int j = 0; j < 4; j++)
                acc[i][j] += av[i] * bv[j];
    }
    float* Cp = C + (size_t)bh * QLEN * KLEN;
    #pragma unroll
    for (int i = 0; i < 4; i++)
        #pragma unroll
        for (int j = 0; j < 4; j++)
            Cp[(size_t)(i0 + tr + i) * KLEN + j0 + tc + j] = acc[i][j];
}

// vec[i, b, n*64+d] = sum_j prob[bh][i][j] * V[j, b, n*64+d]
__global__ __launch_bounds__(256) void bgemm_pv(const float* __restrict__ P,
                                                const float* __restrict__ KV,
                                                float* __restrict__ Cb) {
    __shared__ float Ps[64][72];
    __shared__ float Vs[64][72];
    int bh = blockIdx.z, b = bh >> 4, n = bh & 15;
    int i0 = blockIdx.y * 64;
    const float* Pp = P  + (size_t)bh * QLEN * KLEN;
    const float* Vp = KV + (size_t)b * 2048 + 1024 + n * 64;  // v half
    float* Cp = Cb + (size_t)b * 1024 + n * 64;
    int tid = threadIdx.x;
    int lr = tid >> 4, lc = (tid & 15) * 4;
    int tr = (tid >> 4) * 4, tc = (tid & 15) * 4;
    float acc[4][4] = {};
    for (int k0 = 0; k0 < KLEN; k0 += 64) {
        #pragma unroll
        for (int h = 0; h < 4; h++) {
            int row = lr + 16 * h;
            float4 vp = *(const float4*)(Pp + (size_t)(i0 + row) * KLEN + k0 + lc);
            Ps[lc + 0][row] = vp.x; Ps[lc + 1][row] = vp.y;
            Ps[lc + 2][row] = vp.z; Ps[lc + 3][row] = vp.w;
            float4 vv = *(const float4*)(Vp + (size_t)(k0 + row) * 16384 + lc);
            *(float4*)&Vs[row][lc] = vv;
        }
        __syncthreads();
        #pragma unroll
        for (int j = 0; j < 64; j++) {
            float4 a = *(const float4*)&Ps[j][tr];
            float4 v = *(const float4*)&Vs[j][tc];
            float av[4] = {a.x, a.y, a.z, a.w};
            float vv[4] = {v.x, v.y, v.z, v.w};
            #pragma unroll
            for (int i = 0; i < 4; i++)
                #pragma unroll
                for (int jj = 0; jj < 4; jj++)
                    acc[i][jj] += av[i] * vv[jj];
        }
        __syncthreads();
    }
    #pragma unroll
    for (int i = 0; i < 4; i++)
        #pragma unroll
        for (int j = 0; j < 4; j++)
            Cp[(size_t)(i0 + tr + i) * 8192 + tc + j] = acc[i][j];
}

// ---------------- driver ----------------
extern "C" void kernel_launch(void* const* d_in, const int* in_sizes, int n_in,
                              void* d_out, int out_size) {
    const int*   data   = (const int*)  d_in[0];
    const int*   target = (const int*)  d_in[1];
    const float* memory = (const float*)d_in[2];
    const float* embW   = (const float*)d_in[3];
    const float* rwb    = (const float*)d_in[4];
    const float* rrb    = (const float*)d_in[5];
    const float* Wq     = (const float*)d_in[6];
    const float* Wkv    = (const float*)d_in[7];
    const float* Wr     = (const float*)d_in[8];
    const float* Wo     = (const float*)d_in[9];
    const float* W1     = (const float*)d_in[10];
    const float* b1     = (const float*)d_in[11];
    const float* W2     = (const float*)d_in[12];
    const float* b2     = (const float*)d_in[13];
    const float* ln1g   = (const float*)d_in[14];
    const float* ln1b   = (const float*)d_in[15];
    const float* ln2g   = (const float*)d_in[16];
    const float* ln2b   = (const float*)d_in[17];

    float* out      = (float*)d_out;
    float* loss_out = out;
    float* mems_out = out + MQ;  // [6][512][8][1024]

    float *core, *xmem, *q, *kv, *rk, *pos, *ac, *bd, *vec, *tmp, *ff, *logits;
    cudaGetSymbolAddress((void**)&core,   g_core);
    cudaGetSymbolAddress((void**)&xmem,   g_xmem);
    cudaGetSymbolAddress((void**)&q,      g_q);
    cudaGetSymbolAddress((void**)&kv,     g_kv);
    cudaGetSymbolAddress((void**)&rk,     g_rk);
    cudaGetSymbolAddress((void**)&pos,    g_pos);
    cudaGetSymbolAddress((void**)&ac,     g_ac);
    cudaGetSymbolAddress((void**)&bd,     g_bd);
    cudaGetSymbolAddress((void**)&vec,    g_vec);
    cudaGetSymbolAddress((void**)&tmp,    g_tmp);
    cudaGetSymbolAddress((void**)&ff,     g_ff);
    cudaGetSymbolAddress((void**)&logits, g_logits);

    embed_kernel<<<MQ, 256>>>(data, embW, core, mems_out);    // hids[0]
    pos_kernel<<<KLEN, 256>>>(pos);

    const size_t LROW = (size_t)MQ * DM;  // 4,194,304 elems per layer slab

    for (int l = 0; l < NLAYER; l++) {
        // x_mem = concat(mem[l], core)
        copy4_kernel<<<4096, 256>>>((const float4*)(memory + (size_t)l * LROW), (float4*)xmem, (int)(LROW / 4));
        copy4_kernel<<<4096, 256>>>((const float4*)core, (float4*)(xmem + LROW), (int)(LROW / 4));

        gemm_nn<<<dim3(8, 32), 256>>>(core, Wq + (size_t)l * DM * DM, q, MQ, DM, DM, nullptr, 0);
        gemm_nn<<<dim3(16, 64), 256>>>(xmem, Wkv + (size_t)l * DM * 2 * DM, kv, MK, 2 * DM, DM, nullptr, 0);
        gemm_nn<<<dim3(8, 8), 256>>>(pos, Wr + (size_t)l * DM * DM, rk, KLEN, DM, DM, nullptr, 0);

        // AC = (q + r_w_bias) . k^T,  BD_raw = (q + r_r_bias) . r_k^T
        bgemm_qk<<<dim3(16, 8, 128), 256>>>(q, 1024, 64, 8192, kv, 2048, 64, 16384, rwb, ac);
        bgemm_qk<<<dim3(16, 8, 128), 256>>>(q, 1024, 64, 8192, rk, 0,    64, 1024,  rrb, bd);

        score_softmax_kernel<<<dim3(QLEN, BSZ * NH), 256>>>(ac, bd, ac);   // ac now holds probs
        bgemm_pv<<<dim3(1, 8, 128), 256>>>(ac, kv, vec);

        gemm_nn<<<dim3(8, 32), 256>>>(vec, Wo + (size_t)l * DM * DM, tmp, MQ, DM, DM, nullptr, 0);
        add_ln_kernel<<<MQ, 256>>>(core, tmp, ln1g + l * DM, ln1b + l * DM, core, nullptr);

        gemm_nn<<<dim3(32, 32), 256>>>(core, W1 + (size_t)l * DM * DI, ff, MQ, DI, DM, b1 + (size_t)l * DI, 3);
        gemm_nn<<<dim3(8, 32), 256>>>(ff, W2 + (size_t)l * DI * DM, tmp, MQ, DM, DI, b2 + (size_t)l * DM, 1);

        float* memdst = (l < NLAYER - 1) ? (mems_out + (size_t)(l + 1) * LROW) : nullptr;
        add_ln_kernel<<<MQ, 256>>>(core, tmp, ln2g + l * DM, ln2b + l * DM, core, memdst);
    }

    // tied softmax head + loss
    gemm_nt<<<dim3(VOCAB / 128, MQ / 128), 256>>>(core, embW, logits, MQ, VOCAB, DM);
    loss_kernel<<<MQ, 256>>>(logits, target, loss_out);
}